// round 16
// baseline (speedup 1.0000x reference)
#include <cuda_runtime.h>
#include <cuda_bf16.h>
#include <cuda_fp16.h>
#include <float.h>
#include <stdint.h>

#define D_DIM   64
#define K_CODES 512
#define BLOCK   512          // 16 autonomous warps
#define GRID    148
#define NROWS   65536
#define NGROUPS 4096         // 16-row groups
#define NWARPS  (GRID * 16)
#define WLCAP   128          // worklist slots per warp

// ---- SMEM layout (bytes), ~78KB, 1 CTA/SM ----
#define SM_BH    0            // 4096 uint4 hi-bf16 B fragments (64KB)
#define SM_SN    65536        // 512 floats: exact ||e_k||^2
#define SM_WL    67584        // 16 warps * 128 ints (8KB)
#define SM_WBEST 75776        // 16 warps * 16 u64 (2KB)
#define SM_WCNT  77824        // 16 ints
#define SM_SE2   77888        // int
#define SM_SH2   77892        // int
#define SM_LS    77896        // 16 doubles
#define SMEM_TOTAL 78024

__device__ float        g_embT[K_CODES * D_DIM];   // exact fp32 codebook [k][d]
__device__ double       g_group_sum[NGROUPS];      // per-group loss partials
__device__ unsigned int g_cnt   = 0;
__device__ unsigned int g_wnext = NWARPS;

#define MMA(acc, a, b0, b1)                                                     \
    asm volatile(                                                               \
        "mma.sync.aligned.m16n8k16.row.col.f32.bf16.bf16.f32 "                  \
        "{%0,%1,%2,%3}, {%4,%5,%6,%7}, {%8,%9}, {%0,%1,%2,%3};"                 \
        : "+f"((acc)[0]), "+f"((acc)[1]), "+f"((acc)[2]), "+f"((acc)[3])        \
        : "r"((a)[0]), "r"((a)[1]), "r"((a)[2]), "r"((a)[3]), "r"(b0), "r"(b1))

__device__ __forceinline__ uint32_t pack_bf2(float a, float b) {
    return (uint32_t)__bfloat16_as_ushort(__float2bfloat16(a))
         | ((uint32_t)__bfloat16_as_ushort(__float2bfloat16(b)) << 16);
}

// exact fp32 squared distance row(x) vs code k (fixed summation order)
__device__ __forceinline__ float exact_dist(const float* __restrict__ xrow, int k) {
    const float4* xp = (const float4*)xrow;
    const float4* ep = (const float4*)(g_embT + k * D_DIM);
    float s = 0.f;
    #pragma unroll
    for (int j = 0; j < 16; j++) {
        float4 a = xp[j];
        float4 b = ep[j];
        float dx = a.x - b.x, dy = a.y - b.y, dz = a.z - b.z, dw = a.w - b.w;
        s = fmaf(dx, dx, s); s = fmaf(dy, dy, s);
        s = fmaf(dz, dz, s); s = fmaf(dw, dw, s);
    }
    return s;
}

__global__ void __launch_bounds__(BLOCK, 1)
vq_wa(const float* __restrict__ x, const float* __restrict__ emb,
      float* __restrict__ out, int write_loss)
{
    extern __shared__ char smem[];
    uint4*              sBH4  = (uint4*)(smem + SM_BH);
    float*              snm   = (float*)(smem + SM_SN);
    int*                swl   = (int*)(smem + SM_WL);
    unsigned long long* wbest = (unsigned long long*)(smem + SM_WBEST);
    int*                wcnt  = (int*)(smem + SM_WCNT);
    int*                sSE2  = (int*)(smem + SM_SE2);
    int*                sSH2  = (int*)(smem + SM_SH2);
    double*             sls   = (double*)(smem + SM_LS);

    const int tid  = threadIdx.x;
    const int w    = tid >> 5;
    const int lane = tid & 31;
    const int g    = lane >> 2;
    const int c    = lane & 3;

    if (tid < 2) { sSE2[0] = 0; sSH2[0] = 0; }
    __syncthreads();

    // ---- Prologue 1: hi-bf16 B fragments -> SMEM (uint4 layout) + fp32 transpose ----
    // layout: uint4 idx = nt*64 + lane*2 + (ks>>1); pair (ks&1) in .xy/.zw
    for (int i = tid; i < 8192; i += BLOCK) {
        int nt = i >> 7;
        int ks = (i >> 5) & 3;
        int ln = i & 31;
        int fg = ln >> 2, fc = ln & 3;
        int n  = nt * 8 + fg;
        int d0 = ks * 16 + fc * 2;
        float e00 = __ldg(emb + (d0 + 0) * K_CODES + n);
        float e01 = __ldg(emb + (d0 + 1) * K_CODES + n);
        float e10 = __ldg(emb + (d0 + 8) * K_CODES + n);
        float e11 = __ldg(emb + (d0 + 9) * K_CODES + n);
        uint32_t byte_off = (uint32_t)(nt * 64 + ln * 2 + (ks >> 1)) * 16u + (ks & 1) * 8u;
        *(uint2*)(smem + SM_BH + byte_off) = make_uint2(pack_bf2(e00, e01), pack_bf2(e10, e11));
        g_embT[n * D_DIM + d0]     = e00;
        g_embT[n * D_DIM + d0 + 1] = e01;
        g_embT[n * D_DIM + d0 + 8] = e10;
        g_embT[n * D_DIM + d0 + 9] = e11;
    }
    // ---- Prologue 2: exact code norms + split-error maxima ----
    {
        const int k = tid;   // 512 == BLOCK
        float sn = 0.f, se = 0.f, sh = 0.f;
        #pragma unroll 8
        for (int d = 0; d < D_DIM; d++) {
            float v = emb[d * K_CODES + k];
            float h = __bfloat162float(__float2bfloat16(v));
            float r = v - h;
            sn = fmaf(v, v, sn);
            se = fmaf(r, r, se);
            sh = fmaf(h, h, sh);
        }
        snm[k] = sn;
        atomicMax(sSE2, __float_as_int(se));   // nonneg: int cmp == float cmp
        atomicMax(sSH2, __float_as_int(sh));
    }
    __syncthreads();   // the ONLY CTA barrier before the epilogue

    const float S_e = sqrtf(__int_as_float(*sSE2)) * 1.0001f;  // max ||e-eh||
    const float S_h = sqrtf(__int_as_float(*sSH2)) * 1.0001f;  // max ||eh||

    int grp = blockIdx.x * 16 + w;
    int nextg = 0;

    while (grp < NGROUPS) {
        const int rbase = grp * 16;

        // warp-private state init
        if (lane < 16) wbest[w * 16 + lane] = ~0ull;
        if (lane == 0) wcnt[w] = 0;

        // ---- A fragments (hi split) + per-row norm / residual-norm ----
        uint32_t Ah[4][4];
        float xn0 = 0.f, xn1 = 0.f, rx0 = 0.f, rx1 = 0.f;
        {
            const float* xr0 = x + (size_t)(rbase + g) * D_DIM;
            const float* xr1 = xr0 + 8 * D_DIM;
            #pragma unroll
            for (int ks = 0; ks < 4; ks++) {
                #pragma unroll
                for (int p = 0; p < 2; p++) {
                    int col = 2 * c + 8 * p + 16 * ks;
                    float2 v0 = *(const float2*)(xr0 + col);
                    float2 v1 = *(const float2*)(xr1 + col);
                    xn0 = fmaf(v0.x, v0.x, fmaf(v0.y, v0.y, xn0));
                    xn1 = fmaf(v1.x, v1.x, fmaf(v1.y, v1.y, xn1));
                    float h0x = __bfloat162float(__float2bfloat16(v0.x));
                    float h0y = __bfloat162float(__float2bfloat16(v0.y));
                    float h1x = __bfloat162float(__float2bfloat16(v1.x));
                    float h1y = __bfloat162float(__float2bfloat16(v1.y));
                    float r0x = v0.x - h0x, r0y = v0.y - h0y;
                    float r1x = v1.x - h1x, r1y = v1.y - h1y;
                    rx0 = fmaf(r0x, r0x, fmaf(r0y, r0y, rx0));
                    rx1 = fmaf(r1x, r1x, fmaf(r1y, r1y, rx1));
                    Ah[ks][2 * p]     = pack_bf2(v0.x, v0.y);
                    Ah[ks][2 * p + 1] = pack_bf2(v1.x, v1.y);
                }
            }
        }
        #pragma unroll
        for (int off = 1; off <= 2; off <<= 1) {
            xn0 += __shfl_xor_sync(0xffffffffu, xn0, off);
            xn1 += __shfl_xor_sync(0xffffffffu, xn1, off);
            rx0 += __shfl_xor_sync(0xffffffffu, rx0, off);
            rx1 += __shfl_xor_sync(0xffffffffu, rx1, off);
        }

        // ---- Pass 1: all est distances; track row mins + per-nt min cache ----
        uint32_t mntp[32];      // fp16 min-of-4-est per nt, packed in pairs
        float m0 = FLT_MAX, m1 = FLT_MAX;
        float mn_even = 0.f;
        #pragma unroll 4
        for (int nt = 0; nt < 64; nt++) {
            float acc[4] = {0.f, 0.f, 0.f, 0.f};
            const uint4* pb = sBH4 + nt * 64 + lane * 2;
            uint4 bA = pb[0];
            uint4 bB = pb[1];
            MMA(acc, Ah[0], bA.x, bA.y);
            MMA(acc, Ah[1], bA.z, bA.w);
            MMA(acc, Ah[2], bB.x, bB.y);
            MMA(acc, Ah[3], bB.z, bB.w);
            const int kb = nt * 8 + 2 * c;
            float2 s2 = *(const float2*)(snm + kb);
            float e00 = fmaf(-2.f, acc[0], s2.x);
            float e01 = fmaf(-2.f, acc[1], s2.y);
            float e10 = fmaf(-2.f, acc[2], s2.x);
            float e11 = fmaf(-2.f, acc[3], s2.y);
            float lo0 = fminf(e00, e01);
            float lo1 = fminf(e10, e11);
            m0 = fminf(m0, lo0);
            m1 = fminf(m1, lo1);
            float mn = fminf(lo0, lo1);
            if (nt & 1) {
                __half2 p = __floats2half2_rn(mn_even, mn);
                mntp[nt >> 1] = *(uint32_t*)&p;
            } else {
                mn_even = mn;
            }
        }
        #pragma unroll
        for (int off = 1; off <= 2; off <<= 1) {
            m0 = fminf(m0, __shfl_xor_sync(0xffffffffu, m0, off));
            m1 = fminf(m1, __shfl_xor_sync(0xffffffffu, m1, off));
        }

        // ---- per-row thresholds (rigorous: est_t <= minest + 2*B) ----
        float xns0 = sqrtf(xn0), rxs0 = sqrtf(rx0);
        float xns1 = sqrtf(xn1), rxs1 = sqrtf(rx1);
        const float thr0 = m0 + 2.f * (rxs0 * (S_h + S_e) + (xns0 + rxs0) * S_e) * 2.f + 0.05f;
        const float thr1 = m1 + 2.f * (rxs1 * (S_h + S_e) + (xns1 + rxs1) * S_e) * 2.f + 0.05f;
        const __half2 mthr2 = __float2half2_rn(fmaxf(thr0, thr1) + 0.10f);  // fp16 guard

        __syncwarp();   // wbest/wcnt init visible

        // ---- Pass 2: recompute ONLY hit nt-tiles, append candidates ----
        #pragma unroll 1
        for (int j = 0; j < 32; j++) {
            __half2 le = __hle2(*(__half2*)&mntp[j], mthr2);
            uint32_t mm = *(uint32_t*)&le;
            unsigned blo = __ballot_sync(0xffffffffu, (mm & 0xFFFFu) != 0u);
            unsigned bhi = __ballot_sync(0xffffffffu, (mm >> 16) != 0u);
            #pragma unroll
            for (int h = 0; h < 2; h++) {
                if (h ? !bhi : !blo) continue;
                const int nt = 2 * j + h;
                float acc[4] = {0.f, 0.f, 0.f, 0.f};
                const uint4* pb = sBH4 + nt * 64 + lane * 2;
                uint4 bA = pb[0];
                uint4 bB = pb[1];
                MMA(acc, Ah[0], bA.x, bA.y);
                MMA(acc, Ah[1], bA.z, bA.w);
                MMA(acc, Ah[2], bB.x, bB.y);
                MMA(acc, Ah[3], bB.z, bB.w);
                const int kb = nt * 8 + 2 * c;
                float2 s2 = *(const float2*)(snm + kb);
                float e00 = fmaf(-2.f, acc[0], s2.x);
                float e01 = fmaf(-2.f, acc[1], s2.y);
                float e10 = fmaf(-2.f, acc[2], s2.x);
                float e11 = fmaf(-2.f, acc[3], s2.y);
                if (e00 <= thr0) {
                    int s = atomicAdd(&wcnt[w], 1);
                    if (s < WLCAP) swl[w * WLCAP + s] = (g << 9) | kb;
                }
                if (e01 <= thr0) {
                    int s = atomicAdd(&wcnt[w], 1);
                    if (s < WLCAP) swl[w * WLCAP + s] = (g << 9) | (kb + 1);
                }
                if (e10 <= thr1) {
                    int s = atomicAdd(&wcnt[w], 1);
                    if (s < WLCAP) swl[w * WLCAP + s] = ((g + 8) << 9) | kb;
                }
                if (e11 <= thr1) {
                    int s = atomicAdd(&wcnt[w], 1);
                    if (s < WLCAP) swl[w * WLCAP + s] = ((g + 8) << 9) | (kb + 1);
                }
            }
        }
        __syncwarp();   // worklist complete

        // ---- Rescore: warp-parallel exact fp32, u64 atomicMin ----
        int cnt = wcnt[w];
        if (cnt <= WLCAP) {
            for (int i = lane; i < cnt; i += 32) {
                const int pk   = swl[w * WLCAP + i];
                const int rloc = pk >> 9;
                const int k    = pk & (K_CODES - 1);
                float s = exact_dist(x + (size_t)(rbase + rloc) * D_DIM, k);
                unsigned long long key =
                    ((unsigned long long)(unsigned)__float_as_int(s) << 32) | (unsigned)k;
                atomicMin(&wbest[w * 16 + rloc], key);
            }
        } else {   // provably-correct fallback; practically never taken
            for (int rloc = 0; rloc < 16; rloc++) {
                const float* xrow = x + (size_t)(rbase + rloc) * D_DIM;
                for (int k = lane; k < K_CODES; k += 32) {
                    float s = exact_dist(xrow, k);
                    unsigned long long key =
                        ((unsigned long long)(unsigned)__float_as_int(s) << 32) | (unsigned)k;
                    atomicMin(&wbest[w * 16 + rloc], key);
                }
            }
        }
        __syncwarp();   // wbest final

        // ---- output + group loss: lane L -> row L>>1, half L&1 ----
        {
            const int rloc = lane >> 1;
            const int half = lane & 1;
            unsigned long long key = wbest[w * 16 + rloc];
            const int k = (int)(unsigned)key;
            double dloc = (half == 0) ? (double)__int_as_float((int)(key >> 32)) : 0.0;
            const float4* src = (const float4*)(g_embT + k * D_DIM) + half * 8;
            float4* dst = (float4*)(out + (size_t)(rbase + rloc) * D_DIM) + half * 8;
            #pragma unroll
            for (int j = 0; j < 8; j++) dst[j] = src[j];
            #pragma unroll
            for (int off = 16; off > 0; off >>= 1)
                dloc += __shfl_down_sync(0xffffffffu, dloc, off);
            if (lane == 0) {
                g_group_sum[grp] = dloc;
                nextg = (int)atomicAdd(&g_wnext, 1u);   // steal next group
            }
        }
        grp = __shfl_sync(0xffffffffu, nextg, 0);
        __syncwarp();   // wbest/wcnt reusable next group
    }

    // ---- finalize: last CTA reduces per-group sums in fixed order ----
    __syncthreads();
    __threadfence();
    if (tid == 0) sSE2[0] = (atomicAdd(&g_cnt, 1u) == GRID - 1) ? 1 : 0;
    __syncthreads();
    if (sSE2[0]) {
        __threadfence();
        double s = 0.0;
        #pragma unroll
        for (int i = 0; i < NGROUPS / BLOCK; i++)
            s += g_group_sum[tid + i * BLOCK];
        #pragma unroll
        for (int off = 16; off > 0; off >>= 1)
            s += __shfl_down_sync(0xffffffffu, s, off);
        if (lane == 0) sls[w] = s;
        __syncthreads();
        if (tid == 0) {
            double tot = 0.0;
            #pragma unroll
            for (int i = 0; i < 16; i++) tot += sls[i];
            if (write_loss)
                out[(size_t)NROWS * D_DIM] =
                    (float)(tot * (1.25 / ((double)NROWS * (double)D_DIM)));
            g_cnt   = 0;        // reset for next graph replay
            g_wnext = NWARPS;
        }
    }
}

extern "C" void kernel_launch(void* const* d_in, const int* in_sizes, int n_in,
                              void* d_out, int out_size)
{
    const float* x   = (const float*)d_in[0];
    const float* emb = (const float*)d_in[1];
    float* out = (float*)d_out;

    const int write_loss = (out_size > NROWS * D_DIM) ? 1 : 0;

    static int configured = 0;
    if (!configured) {
        cudaFuncSetAttribute(vq_wa, cudaFuncAttributeMaxDynamicSharedMemorySize, SMEM_TOTAL);
        configured = 1;
    }
    vq_wa<<<GRID, BLOCK, SMEM_TOTAL>>>(x, emb, out, write_loss);
}

// round 17
// speedup vs baseline: 1.0288x; 1.0288x over previous
#include <cuda_runtime.h>
#include <cuda_bf16.h>
#include <cuda_fp16.h>
#include <float.h>
#include <stdint.h>

#define D_DIM   64
#define K_CODES 512
#define BLOCK   512          // 16 autonomous warps
#define GRID    148
#define NROWS   65536
#define NGROUPS 4096         // 16-row groups
#define NWARPS  (GRID * 16)
#define WLCAP   128          // worklist slots per warp

// ---- SMEM layout (bytes), ~94KB, 1 CTA/SM ----
#define SM_BH    0            // 4096 uint4 hi-bf16 B fragments (64KB)
#define SM_SN    65536        // 512 floats: exact ||e_k||^2
#define SM_BM    67584        // blkmin cache: 16 warps * 8 * 32 uint32 (16KB)
#define SM_WL    83968        // 16 warps * 128 ints (8KB)
#define SM_WBEST 92160        // 16 warps * 16 u64 (2KB)
#define SM_WCNT  94208        // 16 ints
#define SM_SE2   94272        // int
#define SM_SH2   94276        // int
#define SM_LS    94280        // 16 doubles
#define SMEM_TOTAL 94408

__device__ float        g_embT[K_CODES * D_DIM];   // exact fp32 codebook [k][d]
__device__ double       g_group_sum[NGROUPS];      // per-group loss partials
__device__ unsigned int g_cnt   = 0;
__device__ unsigned int g_wnext = NWARPS;

#define MMA(acc, a, b0, b1)                                                     \
    asm volatile(                                                               \
        "mma.sync.aligned.m16n8k16.row.col.f32.bf16.bf16.f32 "                  \
        "{%0,%1,%2,%3}, {%4,%5,%6,%7}, {%8,%9}, {%0,%1,%2,%3};"                 \
        : "+f"((acc)[0]), "+f"((acc)[1]), "+f"((acc)[2]), "+f"((acc)[3])        \
        : "r"((a)[0]), "r"((a)[1]), "r"((a)[2]), "r"((a)[3]), "r"(b0), "r"(b1))

__device__ __forceinline__ uint32_t pack_bf2(float a, float b) {
    return (uint32_t)__bfloat16_as_ushort(__float2bfloat16(a))
         | ((uint32_t)__bfloat16_as_ushort(__float2bfloat16(b)) << 16);
}

// exact fp32 squared distance row(x) vs code k (fixed summation order)
__device__ __forceinline__ float exact_dist(const float* __restrict__ xrow, int k) {
    const float4* xp = (const float4*)xrow;
    const float4* ep = (const float4*)(g_embT + k * D_DIM);
    float s = 0.f;
    #pragma unroll
    for (int j = 0; j < 16; j++) {
        float4 a = xp[j];
        float4 b = ep[j];
        float dx = a.x - b.x, dy = a.y - b.y, dz = a.z - b.z, dw = a.w - b.w;
        s = fmaf(dx, dx, s); s = fmaf(dy, dy, s);
        s = fmaf(dz, dz, s); s = fmaf(dw, dw, s);
    }
    return s;
}

__global__ void __launch_bounds__(BLOCK, 1)
vq_wa(const float* __restrict__ x, const float* __restrict__ emb,
      float* __restrict__ out, int write_loss)
{
    extern __shared__ char smem[];
    uint4*              sBH4  = (uint4*)(smem + SM_BH);
    float*              snm   = (float*)(smem + SM_SN);
    uint32_t*           sBM   = (uint32_t*)(smem + SM_BM);
    int*                swl   = (int*)(smem + SM_WL);
    unsigned long long* wbest = (unsigned long long*)(smem + SM_WBEST);
    int*                wcnt  = (int*)(smem + SM_WCNT);
    int*                sSE2  = (int*)(smem + SM_SE2);
    int*                sSH2  = (int*)(smem + SM_SH2);
    double*             sls   = (double*)(smem + SM_LS);

    const int tid  = threadIdx.x;
    const int w    = tid >> 5;
    const int lane = tid & 31;
    const int g    = lane >> 2;
    const int c    = lane & 3;

    if (tid < 2) { sSE2[0] = 0; sSH2[0] = 0; }
    __syncthreads();

    // ---- Prologue 1: hi-bf16 B fragments -> SMEM (uint4 layout) + fp32 transpose ----
    // uint4 idx = nt*64 + lane*2 + (ks>>1); pair (ks&1) in .xy/.zw
    for (int i = tid; i < 8192; i += BLOCK) {
        int nt = i >> 7;
        int ks = (i >> 5) & 3;
        int ln = i & 31;
        int fg = ln >> 2, fc = ln & 3;
        int n  = nt * 8 + fg;
        int d0 = ks * 16 + fc * 2;
        float e00 = __ldg(emb + (d0 + 0) * K_CODES + n);
        float e01 = __ldg(emb + (d0 + 1) * K_CODES + n);
        float e10 = __ldg(emb + (d0 + 8) * K_CODES + n);
        float e11 = __ldg(emb + (d0 + 9) * K_CODES + n);
        uint32_t byte_off = (uint32_t)(nt * 64 + ln * 2 + (ks >> 1)) * 16u + (ks & 1) * 8u;
        *(uint2*)(smem + SM_BH + byte_off) = make_uint2(pack_bf2(e00, e01), pack_bf2(e10, e11));
        g_embT[n * D_DIM + d0]     = e00;
        g_embT[n * D_DIM + d0 + 1] = e01;
        g_embT[n * D_DIM + d0 + 8] = e10;
        g_embT[n * D_DIM + d0 + 9] = e11;
    }
    // ---- Prologue 2: exact code norms + split-error maxima ----
    {
        const int k = tid;   // 512 == BLOCK
        float sn = 0.f, se = 0.f, sh = 0.f;
        #pragma unroll 8
        for (int d = 0; d < D_DIM; d++) {
            float v = emb[d * K_CODES + k];
            float h = __bfloat162float(__float2bfloat16(v));
            float r = v - h;
            sn = fmaf(v, v, sn);
            se = fmaf(r, r, se);
            sh = fmaf(h, h, sh);
        }
        snm[k] = sn;
        atomicMax(sSE2, __float_as_int(se));   // nonneg: int cmp == float cmp
        atomicMax(sSH2, __float_as_int(sh));
    }
    __syncthreads();   // the ONLY CTA barrier before the epilogue

    const float S_e = sqrtf(__int_as_float(*sSE2)) * 1.0001f;  // max ||e-eh||
    const float S_h = sqrtf(__int_as_float(*sSH2)) * 1.0001f;  // max ||eh||

    int grp = blockIdx.x * 16 + w;
    int nextg = 0;

    while (grp < NGROUPS) {
        const int rbase = grp * 16;

        // warp-private state init
        if (lane < 16) wbest[w * 16 + lane] = ~0ull;
        if (lane == 0) wcnt[w] = 0;

        // ---- A fragments (hi split) + per-row norm / residual-norm ----
        uint32_t Ah[4][4];
        float xn0 = 0.f, xn1 = 0.f, rx0 = 0.f, rx1 = 0.f;
        {
            const float* xr0 = x + (size_t)(rbase + g) * D_DIM;
            const float* xr1 = xr0 + 8 * D_DIM;
            #pragma unroll
            for (int ks = 0; ks < 4; ks++) {
                #pragma unroll
                for (int p = 0; p < 2; p++) {
                    int col = 2 * c + 8 * p + 16 * ks;
                    float2 v0 = *(const float2*)(xr0 + col);
                    float2 v1 = *(const float2*)(xr1 + col);
                    xn0 = fmaf(v0.x, v0.x, fmaf(v0.y, v0.y, xn0));
                    xn1 = fmaf(v1.x, v1.x, fmaf(v1.y, v1.y, xn1));
                    float h0x = __bfloat162float(__float2bfloat16(v0.x));
                    float h0y = __bfloat162float(__float2bfloat16(v0.y));
                    float h1x = __bfloat162float(__float2bfloat16(v1.x));
                    float h1y = __bfloat162float(__float2bfloat16(v1.y));
                    float r0x = v0.x - h0x, r0y = v0.y - h0y;
                    float r1x = v1.x - h1x, r1y = v1.y - h1y;
                    rx0 = fmaf(r0x, r0x, fmaf(r0y, r0y, rx0));
                    rx1 = fmaf(r1x, r1x, fmaf(r1y, r1y, rx1));
                    Ah[ks][2 * p]     = pack_bf2(v0.x, v0.y);
                    Ah[ks][2 * p + 1] = pack_bf2(v1.x, v1.y);
                }
            }
        }
        #pragma unroll
        for (int off = 1; off <= 2; off <<= 1) {
            xn0 += __shfl_xor_sync(0xffffffffu, xn0, off);
            xn1 += __shfl_xor_sync(0xffffffffu, xn1, off);
            rx0 += __shfl_xor_sync(0xffffffffu, rx0, off);
            rx1 += __shfl_xor_sync(0xffffffffu, rx1, off);
        }

        // ---- Pass 1: all est distances; row mins + per-4nt block-min -> SMEM ----
        float m0 = FLT_MAX, m1 = FLT_MAX;
        float bm = FLT_MAX, bm_sav = FLT_MAX;
        #pragma unroll 4
        for (int nt = 0; nt < 64; nt++) {
            float acc[4] = {0.f, 0.f, 0.f, 0.f};
            const uint4* pb = sBH4 + nt * 64 + lane * 2;
            uint4 bA = pb[0];
            uint4 bB = pb[1];
            MMA(acc, Ah[0], bA.x, bA.y);
            MMA(acc, Ah[1], bA.z, bA.w);
            MMA(acc, Ah[2], bB.x, bB.y);
            MMA(acc, Ah[3], bB.z, bB.w);
            const int kb = nt * 8 + 2 * c;
            float2 s2 = *(const float2*)(snm + kb);
            float lo0 = fminf(fmaf(-2.f, acc[0], s2.x), fmaf(-2.f, acc[1], s2.y));
            float lo1 = fminf(fmaf(-2.f, acc[2], s2.x), fmaf(-2.f, acc[3], s2.y));
            m0 = fminf(m0, lo0);
            m1 = fminf(m1, lo1);
            bm = fminf(bm, fminf(lo0, lo1));
            if ((nt & 3) == 3) {                 // block of 4 nts complete
                if ((nt & 4) == 0) {
                    bm_sav = bm;
                } else {
                    __half2 p = __floats2half2_rn(bm_sav, bm);
                    sBM[w * 256 + (nt >> 3) * 32 + lane] = *(uint32_t*)&p;
                }
                bm = FLT_MAX;
            }
        }
        #pragma unroll
        for (int off = 1; off <= 2; off <<= 1) {
            m0 = fminf(m0, __shfl_xor_sync(0xffffffffu, m0, off));
            m1 = fminf(m1, __shfl_xor_sync(0xffffffffu, m1, off));
        }

        // ---- per-row thresholds (rigorous: est* <= est_min + 2B) ----
        float xns0 = sqrtf(xn0), rxs0 = sqrtf(rx0);
        float xns1 = sqrtf(xn1), rxs1 = sqrtf(rx1);
        const float thr0 = m0 + 4.f * (rxs0 * (S_h + S_e) + (xns0 + rxs0) * S_e) + 0.05f;
        const float thr1 = m1 + 4.f * (rxs1 * (S_h + S_e) + (xns1 + rxs1) * S_e) + 0.05f;
        const float mthr = fmaxf(thr0, thr1) + 0.10f;   // fp16 round guard

        __syncwarp();   // wbest/wcnt init + sBM visible

        // ---- Pass 2: ballot-skip blocks; recompute only hit blocks ----
        #pragma unroll 1
        for (int jp = 0; jp < 8; jp++) {
            uint32_t pv = sBM[w * 256 + jp * 32 + lane];
            __half2 hv = *(__half2*)&pv;
            float b0v = __low2float(hv);
            float b1v = __high2float(hv);
            unsigned hit0 = __ballot_sync(0xffffffffu, b0v <= mthr);
            unsigned hit1 = __ballot_sync(0xffffffffu, b1v <= mthr);
            #pragma unroll
            for (int h = 0; h < 2; h++) {
                if (h ? !hit1 : !hit0) continue;
                const int blk = 2 * jp + h;
                #pragma unroll 1
                for (int t = 0; t < 4; t++) {
                    const int nt = 4 * blk + t;
                    float acc[4] = {0.f, 0.f, 0.f, 0.f};
                    const uint4* pb = sBH4 + nt * 64 + lane * 2;
                    uint4 bA = pb[0];
                    uint4 bB = pb[1];
                    MMA(acc, Ah[0], bA.x, bA.y);
                    MMA(acc, Ah[1], bA.z, bA.w);
                    MMA(acc, Ah[2], bB.x, bB.y);
                    MMA(acc, Ah[3], bB.z, bB.w);
                    const int kb = nt * 8 + 2 * c;
                    float2 s2 = *(const float2*)(snm + kb);
                    float e00 = fmaf(-2.f, acc[0], s2.x);
                    float e01 = fmaf(-2.f, acc[1], s2.y);
                    float e10 = fmaf(-2.f, acc[2], s2.x);
                    float e11 = fmaf(-2.f, acc[3], s2.y);
                    if (e00 <= thr0) {
                        int s = atomicAdd(&wcnt[w], 1);
                        if (s < WLCAP) swl[w * WLCAP + s] = (g << 9) | kb;
                    }
                    if (e01 <= thr0) {
                        int s = atomicAdd(&wcnt[w], 1);
                        if (s < WLCAP) swl[w * WLCAP + s] = (g << 9) | (kb + 1);
                    }
                    if (e10 <= thr1) {
                        int s = atomicAdd(&wcnt[w], 1);
                        if (s < WLCAP) swl[w * WLCAP + s] = ((g + 8) << 9) | kb;
                    }
                    if (e11 <= thr1) {
                        int s = atomicAdd(&wcnt[w], 1);
                        if (s < WLCAP) swl[w * WLCAP + s] = ((g + 8) << 9) | (kb + 1);
                    }
                }
            }
        }
        __syncwarp();   // worklist complete

        // ---- Rescore: warp-parallel exact fp32, u64 atomicMin ----
        int cnt = wcnt[w];
        if (cnt <= WLCAP) {
            for (int i = lane; i < cnt; i += 32) {
                const int pk   = swl[w * WLCAP + i];
                const int rloc = pk >> 9;
                const int k    = pk & (K_CODES - 1);
                float s = exact_dist(x + (size_t)(rbase + rloc) * D_DIM, k);
                unsigned long long key =
                    ((unsigned long long)(unsigned)__float_as_int(s) << 32) | (unsigned)k;
                atomicMin(&wbest[w * 16 + rloc], key);
            }
        } else {   // provably-correct fallback; practically never taken
            for (int rloc = 0; rloc < 16; rloc++) {
                const float* xrow = x + (size_t)(rbase + rloc) * D_DIM;
                for (int k = lane; k < K_CODES; k += 32) {
                    float s = exact_dist(xrow, k);
                    unsigned long long key =
                        ((unsigned long long)(unsigned)__float_as_int(s) << 32) | (unsigned)k;
                    atomicMin(&wbest[w * 16 + rloc], key);
                }
            }
        }
        __syncwarp();   // wbest final

        // ---- output + group loss: lane L -> row L>>1, half L&1 ----
        {
            const int rloc = lane >> 1;
            const int half = lane & 1;
            unsigned long long key = wbest[w * 16 + rloc];
            const int k = (int)(unsigned)key;
            double dloc = (half == 0) ? (double)__int_as_float((int)(key >> 32)) : 0.0;
            const float4* src = (const float4*)(g_embT + k * D_DIM) + half * 8;
            float4* dst = (float4*)(out + (size_t)(rbase + rloc) * D_DIM) + half * 8;
            #pragma unroll
            for (int j = 0; j < 8; j++) dst[j] = src[j];
            #pragma unroll
            for (int off = 16; off > 0; off >>= 1)
                dloc += __shfl_down_sync(0xffffffffu, dloc, off);
            if (lane == 0) {
                g_group_sum[grp] = dloc;
                nextg = (int)atomicAdd(&g_wnext, 1u);   // steal next group
            }
        }
        grp = __shfl_sync(0xffffffffu, nextg, 0);
        __syncwarp();   // wbest/wcnt/sBM reusable next group
    }

    // ---- finalize: last CTA reduces per-group sums in fixed order ----
    __syncthreads();
    __threadfence();
    if (tid == 0) sSE2[0] = (atomicAdd(&g_cnt, 1u) == GRID - 1) ? 1 : 0;
    __syncthreads();
    if (sSE2[0]) {
        __threadfence();
        double s = 0.0;
        #pragma unroll
        for (int i = 0; i < NGROUPS / BLOCK; i++)
            s += g_group_sum[tid + i * BLOCK];
        #pragma unroll
        for (int off = 16; off > 0; off >>= 1)
            s += __shfl_down_sync(0xffffffffu, s, off);
        if (lane == 0) sls[w] = s;
        __syncthreads();
        if (tid == 0) {
            double tot = 0.0;
            #pragma unroll
            for (int i = 0; i < 16; i++) tot += sls[i];
            if (write_loss)
                out[(size_t)NROWS * D_DIM] =
                    (float)(tot * (1.25 / ((double)NROWS * (double)D_DIM)));
            g_cnt   = 0;        // reset for next graph replay
            g_wnext = NWARPS;
        }
    }
}

extern "C" void kernel_launch(void* const* d_in, const int* in_sizes, int n_in,
                              void* d_out, int out_size)
{
    const float* x   = (const float*)d_in[0];
    const float* emb = (const float*)d_in[1];
    float* out = (float*)d_out;

    const int write_loss = (out_size > NROWS * D_DIM) ? 1 : 0;

    static int configured = 0;
    if (!configured) {
        cudaFuncSetAttribute(vq_wa, cudaFuncAttributeMaxDynamicSharedMemorySize, SMEM_TOTAL);
        configured = 1;
    }
    vq_wa<<<GRID, BLOCK, SMEM_TOTAL>>>(x, emb, out, write_loss);
}